// round 4
// baseline (speedup 1.0000x reference)
#include <cuda_runtime.h>
#include <math.h>

#define NS     131072
#define LE     100
#define LD     50
#define HD     200
#define SPD    202
#define BT     64          // samples per CTA
#define THREADS 256
#define PITCH  204         // row pitch (floats): 816B = 51*16B, conflict-free LDS.128

typedef unsigned long long ull;

__device__ __forceinline__ ull fma2(ull a, ull b, ull c) {
    ull d;
    asm("fma.rn.f32x2 %0, %1, %2, %3;" : "=l"(d) : "l"(a), "l"(b), "l"(c));
    return d;
}
__device__ __forceinline__ float red2(ull v) {
    float lo, hi;
    asm("mov.b64 {%0, %1}, %2;" : "=f"(lo), "=f"(hi) : "l"(v));
    return lo + hi;
}

// dot over N2 8B-units: A from smem (16B-aligned), B global (8B loads)
template <int N2>
__device__ __forceinline__ float dotAB(const float* __restrict__ a, const float* __restrict__ b) {
    const ulonglong2* A2 = (const ulonglong2*)a;
    const ull* B = (const ull*)b;
    ull a0 = 0ull, a1 = 0ull;
#pragma unroll
    for (int i = 0; i < N2 / 2; ++i) {
        ulonglong2 x = A2[i];
        a0 = fma2(x.x, B[2 * i], a0);
        a1 = fma2(x.y, B[2 * i + 1], a1);
    }
    if (N2 & 1) a0 = fma2(((const ull*)a)[N2 - 1], B[N2 - 1], a0);
    return red2(a0) + red2(a1);
}

__device__ __forceinline__ float lrelu(float x) { return x > 0.f ? x : 0.01f * x; }
__device__ __forceinline__ float sigm(float x) { return 1.0f / (1.0f + __expf(-x)); }
__device__ __forceinline__ float tanh_f(float x) {
    float t = __expf(-2.0f * fabsf(x));          // in (0,1], no overflow
    float r = (1.0f - t) / (1.0f + t);
    return copysignf(r, x);
}

// one gate pass: NJ consecutive rows, both samples; low register footprint
template <int NJ>
__device__ __forceinline__ void gate_pass(
    const ulonglong2* __restrict__ hA, const ulonglong2* __restrict__ hB,
    const ulonglong2* __restrict__ W,    // base of row j0 (50 ull2 per row)
    float* __restrict__ outA, float* __restrict__ outB)
{
    ull acc0[NJ], acc1[NJ];
#pragma unroll
    for (int u = 0; u < NJ; ++u) { acc0[u] = 0ull; acc1[u] = 0ull; }
#pragma unroll 1
    for (int i = 0; i < HD / 4; ++i) {     // 50 chunks of 16B
        ulonglong2 ha = hA[i], hb = hB[i];
#pragma unroll
        for (int u = 0; u < NJ; ++u) {
            ulonglong2 wv = W[u * 50 + i];
            acc0[u] = fma2(ha.x, wv.x, acc0[u]);
            acc0[u] = fma2(ha.y, wv.y, acc0[u]);
            acc1[u] = fma2(hb.x, wv.x, acc1[u]);
            acc1[u] = fma2(hb.y, wv.y, acc1[u]);
        }
    }
#pragma unroll
    for (int u = 0; u < NJ; ++u) { outA[u] = red2(acc0[u]); outB[u] = red2(acc1[u]); }
}

// smem layout (floats)
#define OFF_SIG  0
#define OFF_H0   (BT * PITCH)
#define OFF_H1   (2 * BT * PITCH)
#define OFF_XB   (3 * BT * PITCH)
#define OFF_Y2   (OFF_XB + BT * 100)
#define OFF_DIN  (OFF_Y2 + BT * 52)
#define OFF_CT   (OFF_DIN + BT)
#define OFF_ST   (OFF_CT + 100)
#define SMEM_FLOATS (OFF_ST + 100)
#define SMEM_BYTES  (SMEM_FLOATS * 4)

// GRU j-subgroup processing: NJ rows starting at j0, for both samples of this lane
template <int NJ>
__device__ __forceinline__ void gru_group(
    int j0, float dA, float dB,
    const ulonglong2* hA, const ulonglong2* hB,
    const float* __restrict__ hcA, const float* __restrict__ hcB,  // h_old rows
    float* __restrict__ hnA, float* __restrict__ hnB,              // h_new rows
    const float* __restrict__ w_hh,
    const float* __restrict__ w_ih, const float* __restrict__ b_ih,
    const float* __restrict__ b_hh)
{
    const ulonglong2* Wr = (const ulonglong2*)w_hh + (size_t)j0 * 50;
    const ulonglong2* Wz = Wr + 10000;   // +200 rows
    const ulonglong2* Wn = Wr + 20000;   // +400 rows

    float gA[NJ], gB[NJ];        // holds r, then n
    float tA[NJ], tB[NJ];        // scratch (n-pre, then z-pre)

    // r-pass
    gate_pass<NJ>(hA, hB, Wr, gA, gB);
    // n-pass (raw h@Wn)
    gate_pass<NJ>(hA, hB, Wn, tA, tB);
#pragma unroll
    for (int u = 0; u < NJ; ++u) {
        const int j = j0 + u;
        float bhr = b_hh[j], bhn = b_hh[2 * HD + j];
        float xr0 = b_ih[j], xn0 = b_ih[2 * HD + j];
        float wir = w_ih[j], win = w_ih[2 * HD + j];
        float rA = sigm(fmaf(dA, wir, xr0) + gA[u] + bhr);
        float rB = sigm(fmaf(dB, wir, xr0) + gB[u] + bhr);
        gA[u] = tanh_f(fmaf(dA, win, xn0) + rA * (tA[u] + bhn));   // n value
        gB[u] = tanh_f(fmaf(dB, win, xn0) + rB * (tB[u] + bhn));
    }
    // z-pass
    gate_pass<NJ>(hA, hB, Wz, tA, tB);
#pragma unroll
    for (int u = 0; u < NJ; ++u) {
        const int j = j0 + u;
        float bhz = b_hh[HD + j], xz0 = b_ih[HD + j], wiz = w_ih[HD + j];
        float zA = sigm(fmaf(dA, wiz, xz0) + tA[u] + bhz);
        float zB = sigm(fmaf(dB, wiz, xz0) + tB[u] + bhz);
        hnA[j] = (1.f - zA) * gA[u] + zA * hcA[j];
        hnB[j] = (1.f - zB) * gB[u] + zB * hcB[j];
    }
}

__global__ void __launch_bounds__(THREADS, 1)
seq2seq_gru_kernel(
    const float* __restrict__ enc_in,
    const float* __restrict__ enc_w1, const float* __restrict__ enc_b1,
    const float* __restrict__ enc_w2, const float* __restrict__ enc_b2,
    const float* __restrict__ enc_wl, const float* __restrict__ enc_bl,
    const float* __restrict__ w_ih,  const float* __restrict__ w_hh,
    const float* __restrict__ b_ih,  const float* __restrict__ b_hh,
    const float* __restrict__ dec_w1, const float* __restrict__ dec_b1,
    const float* __restrict__ dec_w2, const float* __restrict__ dec_b2,
    const float* __restrict__ dec_w3, const float* __restrict__ dec_b3,
    float* __restrict__ out)
{
    extern __shared__ float sm[];
    float* sig  = sm + OFF_SIG;
    float* hb0  = sm + OFF_H0;
    float* hb1  = sm + OFF_H1;
    float* xbuf = sm + OFF_XB;
    float* y2b  = sm + OFF_Y2;
    float* din  = sm + OFF_DIN;
    float* ctab = sm + OFF_CT;
    float* stab = sm + OFF_ST;

    const int tid  = threadIdx.x;
    const int lane = tid & 31;
    const int w    = tid >> 5;             // 8 warps
    const int cta  = blockIdx.x;
    const float* inbase = enc_in + (size_t)cta * BT * LE;

    // ---- stage raw signal ----
    for (int idx = tid; idx < BT * LE; idx += THREADS) {
        int s = idx / LE, t = idx - s * LE;
        sig[s * PITCH + t] = inbase[idx];
    }
    if (tid < 100) {
        float u = (float)tid / 50.0f;
        ctab[tid] = cospif(u);
        stab[tid] = sinpif(u);
    }
    if (tid < BT) din[tid] = inbase[tid * LE + (LE - 1)];
    __syncthreads();

    // ---- DFT features ----
    for (int kk = 0; kk < 7; ++kk) {
        int k = w + 8 * kk;
        if (k < 51) {
#pragma unroll
            for (int p = 0; p < 2; ++p) {
                int s = lane + 32 * p;
                const float* xr = sig + s * PITCH;
                float re = 0.f, im = 0.f;
                int m = 0;
                for (int t = 0; t < LE; ++t) {
                    float xv = xr[t];
                    re += xv * ctab[m];
                    im -= xv * stab[m];
                    m += k; if (m >= 100) m -= 100;
                }
                re *= 0.01f; im *= 0.01f;
                if (k == 0 || k == 50) im = 0.0f;
                sig[s * PITCH + 100 + k] = sqrtf(re * re + im * im);
                sig[s * PITCH + 151 + k] = atan2f(im, re);
            }
        }
    }
    __syncthreads();

    // ---- encoder layer 1: [202]->[100] ----
    for (int ii = 0; ii < 13; ++ii) {
        int i = w + 8 * ii;
        if (i < 100) {
            float b = enc_b1[i];
            const float* wr = enc_w1 + (size_t)i * SPD;
#pragma unroll
            for (int p = 0; p < 2; ++p) {
                int s = lane + 32 * p;
                xbuf[s * 100 + i] = lrelu(dotAB<101>(sig + s * PITCH, wr) + b);
            }
        }
    }
    __syncthreads();
    // ---- encoder layer 2: [100]->[202] ----
    for (int ii = 0; ii < 26; ++ii) {
        int i = w + 8 * ii;
        if (i < SPD) {
            float b = enc_b2[i];
            const float* wr = enc_w2 + (size_t)i * 100;
#pragma unroll
            for (int p = 0; p < 2; ++p) {
                int s = lane + 32 * p;
                sig[s * PITCH + i] = lrelu(dotAB<50>(xbuf + s * 100, wr) + b);
            }
        }
    }
    __syncthreads();
    // ---- encoder final: [202]->[200] -> h0 ----
    for (int ii = 0; ii < 25; ++ii) {
        int i = w + 8 * ii;
        float b = enc_bl[i];
        const float* wr = enc_wl + (size_t)i * SPD;
#pragma unroll
        for (int p = 0; p < 2; ++p) {
            int s = lane + 32 * p;
            hb0[s * PITCH + i] = dotAB<101>(sig + s * PITCH, wr) + b;
        }
    }
    __syncthreads();

    const int jbase = w * 25;   // warp owns 25 consecutive j

    // ---- decoder loop ----
    for (int t = 0; t < LD; ++t) {
        float* hc = (t & 1) ? hb1 : hb0;
        float* hn = (t & 1) ? hb0 : hb1;

        const float dA = din[lane];
        const float dB = din[lane + 32];

        const ulonglong2* hA = (const ulonglong2*)(hc + lane * PITCH);
        const ulonglong2* hB = (const ulonglong2*)(hc + (lane + 32) * PITCH);
        const float* hcA = hc + lane * PITCH;
        const float* hcB = hc + (lane + 32) * PITCH;
        float* hnA = hn + lane * PITCH;
        float* hnB = hn + (lane + 32) * PITCH;

        gru_group<13>(jbase,      dA, dB, hA, hB, hcA, hcB, hnA, hnB,
                      w_hh, w_ih, b_ih, b_hh);
        gru_group<12>(jbase + 13, dA, dB, hA, hB, hcA, hcB, hnA, hnB,
                      w_hh, w_ih, b_ih, b_hh);
        __syncthreads();

        // dec layer 1: [200]->[100]
        for (int ii = 0; ii < 13; ++ii) {
            int i = w + 8 * ii;
            if (i < 100) {
                float b = dec_b1[i];
                const float* wr1 = dec_w1 + (size_t)i * HD;
#pragma unroll
                for (int p = 0; p < 2; ++p) {
                    int s = lane + 32 * p;
                    xbuf[s * 100 + i] = lrelu(dotAB<100>(hn + s * PITCH, wr1) + b);
                }
            }
        }
        __syncthreads();
        // dec layer 2: [100]->[50]
        for (int ii = 0; ii < 7; ++ii) {
            int i = w + 8 * ii;
            if (i < 50) {
                float b = dec_b2[i];
                const float* wr2 = dec_w2 + (size_t)i * 100;
#pragma unroll
                for (int p = 0; p < 2; ++p) {
                    int s = lane + 32 * p;
                    y2b[s * 52 + i] = lrelu(dotAB<50>(xbuf + s * 100, wr2) + b);
                }
            }
        }
        __syncthreads();
        // dec layer 3: [50]->[1]
        if (tid < BT) {
            int s = tid;
            float v = dotAB<25>(y2b + s * 52, dec_w3) + dec_b3[0];
            out[((size_t)(cta * BT + s)) * LD + t] = v;
            din[s] = v;
        }
        __syncthreads();
    }
}

extern "C" void kernel_launch(void* const* d_in, const int* in_sizes, int n_in,
                              void* d_out, int out_size) {
    const float* enc_in = (const float*)d_in[0];
    const float* enc_w1 = (const float*)d_in[1];
    const float* enc_b1 = (const float*)d_in[2];
    const float* enc_w2 = (const float*)d_in[3];
    const float* enc_b2 = (const float*)d_in[4];
    const float* enc_wl = (const float*)d_in[5];
    const float* enc_bl = (const float*)d_in[6];
    const float* w_ih   = (const float*)d_in[7];
    const float* w_hh   = (const float*)d_in[8];
    const float* b_ih   = (const float*)d_in[9];
    const float* b_hh   = (const float*)d_in[10];
    const float* dec_w1 = (const float*)d_in[11];
    const float* dec_b1 = (const float*)d_in[12];
    const float* dec_w2 = (const float*)d_in[13];
    const float* dec_b2 = (const float*)d_in[14];
    const float* dec_w3 = (const float*)d_in[15];
    const float* dec_b3 = (const float*)d_in[16];
    float* out = (float*)d_out;

    cudaFuncSetAttribute(seq2seq_gru_kernel,
                         cudaFuncAttributeMaxDynamicSharedMemorySize, SMEM_BYTES);
    seq2seq_gru_kernel<<<NS / BT, THREADS, SMEM_BYTES>>>(
        enc_in, enc_w1, enc_b1, enc_w2, enc_b2, enc_wl, enc_bl,
        w_ih, w_hh, b_ih, b_hh,
        dec_w1, dec_b1, dec_w2, dec_b2, dec_w3, dec_b3, out);
}

// round 5
// speedup vs baseline: 1.2167x; 1.2167x over previous
#include <cuda_runtime.h>
#include <math.h>

#define NS     131072
#define LE     100
#define LD     50
#define HD     200
#define SPD    202
#define BT     64          // samples per CTA
#define THREADS 256
#define PITCH  204         // row pitch (floats): 816B, 16B aligned, conflict-free LDS.128

typedef unsigned long long ull;

__device__ __forceinline__ ull fma2(ull a, ull b, ull c) {
    ull d;
    asm("fma.rn.f32x2 %0, %1, %2, %3;" : "=l"(d) : "l"(a), "l"(b), "l"(c));
    return d;
}
__device__ __forceinline__ float red2(ull v) {
    float lo, hi;
    asm("mov.b64 {%0, %1}, %2;" : "=f"(lo), "=f"(hi) : "l"(v));
    return lo + hi;
}

// dot over N2 8B-units: A from smem (16B-aligned), B global (8B loads)
template <int N2>
__device__ __forceinline__ float dotAB(const float* __restrict__ a, const float* __restrict__ b) {
    const ulonglong2* A2 = (const ulonglong2*)a;
    const ull* B = (const ull*)b;
    ull a0 = 0ull, a1 = 0ull;
#pragma unroll
    for (int i = 0; i < N2 / 2; ++i) {
        ulonglong2 x = A2[i];
        a0 = fma2(x.x, B[2 * i], a0);
        a1 = fma2(x.y, B[2 * i + 1], a1);
    }
    if (N2 & 1) a0 = fma2(((const ull*)a)[N2 - 1], B[N2 - 1], a0);
    return red2(a0) + red2(a1);
}

__device__ __forceinline__ float lrelu(float x) { return x > 0.f ? x : 0.01f * x; }
__device__ __forceinline__ float sigm(float x) { return 1.0f / (1.0f + __expf(-x)); }
__device__ __forceinline__ float tanh_f(float x) {
    float t = __expf(-2.0f * fabsf(x));
    float r = (1.0f - t) / (1.0f + t);
    return copysignf(r, x);
}

#define JG 5

// two-gate pass (r and z): NJ=JG rows each from W1 and W2, both samples
__device__ __forceinline__ void pass2g(
    const ulonglong2* __restrict__ hA, const ulonglong2* __restrict__ hB,
    const ulonglong2* __restrict__ W1, const ulonglong2* __restrict__ W2,
    float (&o1A)[JG], float (&o1B)[JG], float (&o2A)[JG], float (&o2B)[JG])
{
    ull a1[JG][2], a2[JG][2];
#pragma unroll
    for (int u = 0; u < JG; ++u) { a1[u][0] = a1[u][1] = 0ull; a2[u][0] = a2[u][1] = 0ull; }
#pragma unroll 1
    for (int i = 0; i < HD / 4; ++i) {
        ulonglong2 ha = hA[i], hb = hB[i];
#pragma unroll
        for (int u = 0; u < JG; ++u) {
            ulonglong2 wv = W1[u * 50 + i];
            a1[u][0] = fma2(ha.x, wv.x, a1[u][0]);
            a1[u][0] = fma2(ha.y, wv.y, a1[u][0]);
            a1[u][1] = fma2(hb.x, wv.x, a1[u][1]);
            a1[u][1] = fma2(hb.y, wv.y, a1[u][1]);
        }
#pragma unroll
        for (int u = 0; u < JG; ++u) {
            ulonglong2 wv = W2[u * 50 + i];
            a2[u][0] = fma2(ha.x, wv.x, a2[u][0]);
            a2[u][0] = fma2(ha.y, wv.y, a2[u][0]);
            a2[u][1] = fma2(hb.x, wv.x, a2[u][1]);
            a2[u][1] = fma2(hb.y, wv.y, a2[u][1]);
        }
    }
#pragma unroll
    for (int u = 0; u < JG; ++u) {
        o1A[u] = red2(a1[u][0]); o1B[u] = red2(a1[u][1]);
        o2A[u] = red2(a2[u][0]); o2B[u] = red2(a2[u][1]);
    }
}

// one-gate pass (n)
__device__ __forceinline__ void pass1g(
    const ulonglong2* __restrict__ hA, const ulonglong2* __restrict__ hB,
    const ulonglong2* __restrict__ W,
    float (&oA)[JG], float (&oB)[JG])
{
    ull a[JG][2];
#pragma unroll
    for (int u = 0; u < JG; ++u) { a[u][0] = a[u][1] = 0ull; }
#pragma unroll 1
    for (int i = 0; i < HD / 4; ++i) {
        ulonglong2 ha = hA[i], hb = hB[i];
#pragma unroll
        for (int u = 0; u < JG; ++u) {
            ulonglong2 wv = W[u * 50 + i];
            a[u][0] = fma2(ha.x, wv.x, a[u][0]);
            a[u][0] = fma2(ha.y, wv.y, a[u][0]);
            a[u][1] = fma2(hb.x, wv.x, a[u][1]);
            a[u][1] = fma2(hb.y, wv.y, a[u][1]);
        }
    }
#pragma unroll
    for (int u = 0; u < JG; ++u) { oA[u] = red2(a[u][0]); oB[u] = red2(a[u][1]); }
}

// smem layout (floats): two big buffers + small tables.
// bufA: sig during encoder; then h ping-pong partner.
// bufB: xbuf during encoder, then h0, then h ping-pong partner.
// During decode, the CURRENT hc buffer is dead after the GRU phase ->
// xbuf (64*100) and y2b (64*52) overlay it.
#define OFF_A    0
#define OFF_B    (BT * PITCH)
#define OFF_DIN  (2 * BT * PITCH)
#define OFF_CT   (OFF_DIN + BT)
#define OFF_ST   (OFF_CT + 100)
#define SMEM_FLOATS (OFF_ST + 100)
#define SMEM_BYTES  (SMEM_FLOATS * 4)

__global__ void __launch_bounds__(THREADS, 2)
seq2seq_gru_kernel(
    const float* __restrict__ enc_in,
    const float* __restrict__ enc_w1, const float* __restrict__ enc_b1,
    const float* __restrict__ enc_w2, const float* __restrict__ enc_b2,
    const float* __restrict__ enc_wl, const float* __restrict__ enc_bl,
    const float* __restrict__ w_ih,  const float* __restrict__ w_hh,
    const float* __restrict__ b_ih,  const float* __restrict__ b_hh,
    const float* __restrict__ dec_w1, const float* __restrict__ dec_b1,
    const float* __restrict__ dec_w2, const float* __restrict__ dec_b2,
    const float* __restrict__ dec_w3, const float* __restrict__ dec_b3,
    float* __restrict__ out)
{
    extern __shared__ float sm[];
    float* bufA = sm + OFF_A;
    float* bufB = sm + OFF_B;
    float* din  = sm + OFF_DIN;
    float* ctab = sm + OFF_CT;
    float* stab = sm + OFF_ST;

    const int tid  = threadIdx.x;
    const int lane = tid & 31;
    const int w    = tid >> 5;             // 8 warps
    const int cta  = blockIdx.x;
    const float* inbase = enc_in + (size_t)cta * BT * LE;

    float* sig = bufA;

    // ---- stage raw signal into sig ----
    for (int idx = tid; idx < BT * LE; idx += THREADS) {
        int s = idx / LE, t = idx - s * LE;
        sig[s * PITCH + t] = inbase[idx];
    }
    if (tid < 100) {
        float u = (float)tid / 50.0f;
        ctab[tid] = cospif(u);
        stab[tid] = sinpif(u);
    }
    if (tid < BT) din[tid] = inbase[tid * LE + (LE - 1)];
    __syncthreads();

    // ---- DFT features ----
    for (int kk = 0; kk < 7; ++kk) {
        int k = w + 8 * kk;
        if (k < 51) {
#pragma unroll
            for (int p = 0; p < 2; ++p) {
                int s = lane + 32 * p;
                const float* xr = sig + s * PITCH;
                float re = 0.f, im = 0.f;
                int m = 0;
                for (int t = 0; t < LE; ++t) {
                    float xv = xr[t];
                    re += xv * ctab[m];
                    im -= xv * stab[m];
                    m += k; if (m >= 100) m -= 100;
                }
                re *= 0.01f; im *= 0.01f;
                if (k == 0 || k == 50) im = 0.0f;
                sig[s * PITCH + 100 + k] = sqrtf(re * re + im * im);
                sig[s * PITCH + 151 + k] = atan2f(im, re);
            }
        }
    }
    __syncthreads();

    // ---- encoder layer 1: [202]->[100] -> xbuf (in bufB) ----
    {
        float* xbuf = bufB;
        for (int ii = 0; ii < 13; ++ii) {
            int i = w + 8 * ii;
            if (i < 100) {
                float b = enc_b1[i];
                const float* wr = enc_w1 + (size_t)i * SPD;
#pragma unroll
                for (int p = 0; p < 2; ++p) {
                    int s = lane + 32 * p;
                    xbuf[s * 100 + i] = lrelu(dotAB<101>(sig + s * PITCH, wr) + b);
                }
            }
        }
        __syncthreads();
        // ---- encoder layer 2: [100]->[202] back into sig ----
        for (int ii = 0; ii < 26; ++ii) {
            int i = w + 8 * ii;
            if (i < SPD) {
                float b = enc_b2[i];
                const float* wr = enc_w2 + (size_t)i * 100;
#pragma unroll
                for (int p = 0; p < 2; ++p) {
                    int s = lane + 32 * p;
                    sig[s * PITCH + i] = lrelu(dotAB<50>(xbuf + s * 100, wr) + b);
                }
            }
        }
        __syncthreads();
    }
    // ---- encoder final: [202]->[200] -> h0 in bufB ----
    for (int ii = 0; ii < 25; ++ii) {
        int i = w + 8 * ii;
        float b = enc_bl[i];
        const float* wr = enc_wl + (size_t)i * SPD;
#pragma unroll
        for (int p = 0; p < 2; ++p) {
            int s = lane + 32 * p;
            bufB[s * PITCH + i] = dotAB<101>(sig + s * PITCH, wr) + b;
        }
    }
    __syncthreads();

    const int jbase = w * 25;   // warp owns 25 consecutive j

    // ---- decoder loop; h ping-pongs bufB (t even: hc) <-> bufA ----
    for (int t = 0; t < LD; ++t) {
        float* hc = (t & 1) ? bufA : bufB;
        float* hn = (t & 1) ? bufB : bufA;

        const float dA = din[lane];
        const float dB = din[lane + 32];

        const ulonglong2* hA = (const ulonglong2*)(hc + lane * PITCH);
        const ulonglong2* hB = (const ulonglong2*)(hc + (lane + 32) * PITCH);
        const float* hcA = hc + lane * PITCH;
        const float* hcB = hc + (lane + 32) * PITCH;
        float* hnA = hn + lane * PITCH;
        float* hnB = hn + (lane + 32) * PITCH;

        for (int g = 0; g < 5; ++g) {
            const int j0 = jbase + g * JG;
            const ulonglong2* Wr = (const ulonglong2*)w_hh + (size_t)j0 * 50;
            const ulonglong2* Wz = Wr + 10000;
            const ulonglong2* Wn = Wr + 20000;

            float rA[JG], rB[JG], zA[JG], zB[JG];
            pass2g(hA, hB, Wr, Wz, rA, rB, zA, zB);
#pragma unroll
            for (int u = 0; u < JG; ++u) {
                const int j = j0 + u;
                float bhr = b_hh[j], xr0 = b_ih[j], wir = w_ih[j];
                float bhz = b_hh[HD + j], xz0 = b_ih[HD + j], wiz = w_ih[HD + j];
                rA[u] = sigm(fmaf(dA, wir, xr0) + rA[u] + bhr);
                rB[u] = sigm(fmaf(dB, wir, xr0) + rB[u] + bhr);
                zA[u] = sigm(fmaf(dA, wiz, xz0) + zA[u] + bhz);
                zB[u] = sigm(fmaf(dB, wiz, xz0) + zB[u] + bhz);
            }
            float nA[JG], nB[JG];
            pass1g(hA, hB, Wn, nA, nB);
#pragma unroll
            for (int u = 0; u < JG; ++u) {
                const int j = j0 + u;
                float bhn = b_hh[2 * HD + j], xn0 = b_ih[2 * HD + j], win = w_ih[2 * HD + j];
                float nvA = tanh_f(fmaf(dA, win, xn0) + rA[u] * (nA[u] + bhn));
                float nvB = tanh_f(fmaf(dB, win, xn0) + rB[u] * (nB[u] + bhn));
                hnA[j] = (1.f - zA[u]) * nvA + zA[u] * hcA[j];
                hnB[j] = (1.f - zB[u]) * nvB + zB[u] * hcB[j];
            }
        }
        __syncthreads();

        // hc is now dead: overlay scratch there
        float* xbuf = hc;               // 64*100
        float* y2b  = hc + BT * 100;    // 64*52

        // dec layer 1: [200]->[100]
        for (int ii = 0; ii < 13; ++ii) {
            int i = w + 8 * ii;
            if (i < 100) {
                float b = dec_b1[i];
                const float* wr1 = dec_w1 + (size_t)i * HD;
#pragma unroll
                for (int p = 0; p < 2; ++p) {
                    int s = lane + 32 * p;
                    xbuf[s * 100 + i] = lrelu(dotAB<100>(hn + s * PITCH, wr1) + b);
                }
            }
        }
        __syncthreads();
        // dec layer 2: [100]->[50]
        for (int ii = 0; ii < 7; ++ii) {
            int i = w + 8 * ii;
            if (i < 50) {
                float b = dec_b2[i];
                const float* wr2 = dec_w2 + (size_t)i * 100;
#pragma unroll
                for (int p = 0; p < 2; ++p) {
                    int s = lane + 32 * p;
                    y2b[s * 52 + i] = lrelu(dotAB<50>(xbuf + s * 100, wr2) + b);
                }
            }
        }
        __syncthreads();
        // dec layer 3: [50]->[1]
        if (tid < BT) {
            int s = tid;
            float v = dotAB<25>(y2b + s * 52, dec_w3) + dec_b3[0];
            out[((size_t)(cta * BT + s)) * LD + t] = v;
            din[s] = v;
        }
        __syncthreads();
    }
}

extern "C" void kernel_launch(void* const* d_in, const int* in_sizes, int n_in,
                              void* d_out, int out_size) {
    const float* enc_in = (const float*)d_in[0];
    const float* enc_w1 = (const float*)d_in[1];
    const float* enc_b1 = (const float*)d_in[2];
    const float* enc_w2 = (const float*)d_in[3];
    const float* enc_b2 = (const float*)d_in[4];
    const float* enc_wl = (const float*)d_in[5];
    const float* enc_bl = (const float*)d_in[6];
    const float* w_ih   = (const float*)d_in[7];
    const float* w_hh   = (const float*)d_in[8];
    const float* b_ih   = (const float*)d_in[9];
    const float* b_hh   = (const float*)d_in[10];
    const float* dec_w1 = (const float*)d_in[11];
    const float* dec_b1 = (const float*)d_in[12];
    const float* dec_w2 = (const float*)d_in[13];
    const float* dec_b2 = (const float*)d_in[14];
    const float* dec_w3 = (const float*)d_in[15];
    const float* dec_b3 = (const float*)d_in[16];
    float* out = (float*)d_out;

    cudaFuncSetAttribute(seq2seq_gru_kernel,
                         cudaFuncAttributeMaxDynamicSharedMemorySize, SMEM_BYTES);
    seq2seq_gru_kernel<<<NS / BT, THREADS, SMEM_BYTES>>>(
        enc_in, enc_w1, enc_b1, enc_w2, enc_b2, enc_wl, enc_bl,
        w_ih, w_hh, b_ih, b_hh,
        dec_w1, dec_b1, dec_w2, dec_b2, dec_w3, dec_b3, out);
}

// round 6
// speedup vs baseline: 1.2169x; 1.0002x over previous
#include <cuda_runtime.h>
#include <math.h>

#define NS     131072
#define LE     100
#define LD     50
#define HD     200
#define SPD    202
#define BT     64          // samples per CTA
#define THREADS 256
#define PITCH  204         // row pitch (floats): 816B, 16B aligned, conflict-free LDS.128

typedef unsigned long long ull;

__device__ __forceinline__ ull fma2(ull a, ull b, ull c) {
    ull d;
    asm("fma.rn.f32x2 %0, %1, %2, %3;" : "=l"(d) : "l"(a), "l"(b), "l"(c));
    return d;
}
__device__ __forceinline__ float red2(ull v) {
    float lo, hi;
    asm("mov.b64 {%0, %1}, %2;" : "=f"(lo), "=f"(hi) : "l"(v));
    return lo + hi;
}

// dot over N2 8B-units: A from smem (16B-aligned), B global (8B loads)
template <int N2>
__device__ __forceinline__ float dotAB(const float* __restrict__ a, const float* __restrict__ b) {
    const ulonglong2* A2 = (const ulonglong2*)a;
    const ull* B = (const ull*)b;
    ull a0 = 0ull, a1 = 0ull;
#pragma unroll
    for (int i = 0; i < N2 / 2; ++i) {
        ulonglong2 x = A2[i];
        a0 = fma2(x.x, B[2 * i], a0);
        a1 = fma2(x.y, B[2 * i + 1], a1);
    }
    if (N2 & 1) a0 = fma2(((const ull*)a)[N2 - 1], B[N2 - 1], a0);
    return red2(a0) + red2(a1);
}

__device__ __forceinline__ float lrelu(float x) { return x > 0.f ? x : 0.01f * x; }
__device__ __forceinline__ float sigm(float x) { return 1.0f / (1.0f + __expf(-x)); }
__device__ __forceinline__ float tanh_f(float x) {
    float t = __expf(-2.0f * fabsf(x));
    float r = (1.0f - t) / (1.0f + t);
    return copysignf(r, x);
}

#define JG 5

// two-gate pass (r and z): NJ=JG rows each from W1 and W2, both samples
__device__ __forceinline__ void pass2g(
    const ulonglong2* __restrict__ hA, const ulonglong2* __restrict__ hB,
    const ulonglong2* __restrict__ W1, const ulonglong2* __restrict__ W2,
    float (&o1A)[JG], float (&o1B)[JG], float (&o2A)[JG], float (&o2B)[JG])
{
    ull a1[JG][2], a2[JG][2];
#pragma unroll
    for (int u = 0; u < JG; ++u) { a1[u][0] = a1[u][1] = 0ull; a2[u][0] = a2[u][1] = 0ull; }
#pragma unroll 1
    for (int i = 0; i < HD / 4; ++i) {
        ulonglong2 ha = hA[i], hb = hB[i];
#pragma unroll
        for (int u = 0; u < JG; ++u) {
            ulonglong2 wv = W1[u * 50 + i];
            a1[u][0] = fma2(ha.x, wv.x, a1[u][0]);
            a1[u][0] = fma2(ha.y, wv.y, a1[u][0]);
            a1[u][1] = fma2(hb.x, wv.x, a1[u][1]);
            a1[u][1] = fma2(hb.y, wv.y, a1[u][1]);
        }
#pragma unroll
        for (int u = 0; u < JG; ++u) {
            ulonglong2 wv = W2[u * 50 + i];
            a2[u][0] = fma2(ha.x, wv.x, a2[u][0]);
            a2[u][0] = fma2(ha.y, wv.y, a2[u][0]);
            a2[u][1] = fma2(hb.x, wv.x, a2[u][1]);
            a2[u][1] = fma2(hb.y, wv.y, a2[u][1]);
        }
    }
#pragma unroll
    for (int u = 0; u < JG; ++u) {
        o1A[u] = red2(a1[u][0]); o1B[u] = red2(a1[u][1]);
        o2A[u] = red2(a2[u][0]); o2B[u] = red2(a2[u][1]);
    }
}

// one-gate pass (n)
__device__ __forceinline__ void pass1g(
    const ulonglong2* __restrict__ hA, const ulonglong2* __restrict__ hB,
    const ulonglong2* __restrict__ W,
    float (&oA)[JG], float (&oB)[JG])
{
    ull a[JG][2];
#pragma unroll
    for (int u = 0; u < JG; ++u) { a[u][0] = a[u][1] = 0ull; }
#pragma unroll 1
    for (int i = 0; i < HD / 4; ++i) {
        ulonglong2 ha = hA[i], hb = hB[i];
#pragma unroll
        for (int u = 0; u < JG; ++u) {
            ulonglong2 wv = W[u * 50 + i];
            a[u][0] = fma2(ha.x, wv.x, a[u][0]);
            a[u][0] = fma2(ha.y, wv.y, a[u][0]);
            a[u][1] = fma2(hb.x, wv.x, a[u][1]);
            a[u][1] = fma2(hb.y, wv.y, a[u][1]);
        }
    }
#pragma unroll
    for (int u = 0; u < JG; ++u) { oA[u] = red2(a[u][0]); oB[u] = red2(a[u][1]); }
}

// smem layout (floats): two big buffers + small tables.
// bufA: sig during encoder; then h ping-pong partner.
// bufB: xbuf during encoder, then h0, then h ping-pong partner.
// During decode, the CURRENT hc buffer is dead after the GRU phase ->
// xbuf (64*100) and y2b (64*52) overlay it.
#define OFF_A    0
#define OFF_B    (BT * PITCH)
#define OFF_DIN  (2 * BT * PITCH)
#define OFF_CT   (OFF_DIN + BT)
#define OFF_ST   (OFF_CT + 100)
#define SMEM_FLOATS (OFF_ST + 100)
#define SMEM_BYTES  (SMEM_FLOATS * 4)

__global__ void __launch_bounds__(THREADS, 2)
seq2seq_gru_kernel(
    const float* __restrict__ enc_in,
    const float* __restrict__ enc_w1, const float* __restrict__ enc_b1,
    const float* __restrict__ enc_w2, const float* __restrict__ enc_b2,
    const float* __restrict__ enc_wl, const float* __restrict__ enc_bl,
    const float* __restrict__ w_ih,  const float* __restrict__ w_hh,
    const float* __restrict__ b_ih,  const float* __restrict__ b_hh,
    const float* __restrict__ dec_w1, const float* __restrict__ dec_b1,
    const float* __restrict__ dec_w2, const float* __restrict__ dec_b2,
    const float* __restrict__ dec_w3, const float* __restrict__ dec_b3,
    float* __restrict__ out)
{
    extern __shared__ float sm[];
    float* bufA = sm + OFF_A;
    float* bufB = sm + OFF_B;
    float* din  = sm + OFF_DIN;
    float* ctab = sm + OFF_CT;
    float* stab = sm + OFF_ST;

    const int tid  = threadIdx.x;
    const int lane = tid & 31;
    const int w    = tid >> 5;             // 8 warps
    const int cta  = blockIdx.x;
    const float* inbase = enc_in + (size_t)cta * BT * LE;

    float* sig = bufA;

    // ---- stage raw signal into sig ----
    for (int idx = tid; idx < BT * LE; idx += THREADS) {
        int s = idx / LE, t = idx - s * LE;
        sig[s * PITCH + t] = inbase[idx];
    }
    if (tid < 100) {
        float u = (float)tid / 50.0f;
        ctab[tid] = cospif(u);
        stab[tid] = sinpif(u);
    }
    if (tid < BT) din[tid] = inbase[tid * LE + (LE - 1)];
    __syncthreads();

    // ---- DFT features ----
    for (int kk = 0; kk < 7; ++kk) {
        int k = w + 8 * kk;
        if (k < 51) {
#pragma unroll
            for (int p = 0; p < 2; ++p) {
                int s = lane + 32 * p;
                const float* xr = sig + s * PITCH;
                float re = 0.f, im = 0.f;
                int m = 0;
                for (int t = 0; t < LE; ++t) {
                    float xv = xr[t];
                    re += xv * ctab[m];
                    im -= xv * stab[m];
                    m += k; if (m >= 100) m -= 100;
                }
                re *= 0.01f; im *= 0.01f;
                if (k == 0 || k == 50) im = 0.0f;
                sig[s * PITCH + 100 + k] = sqrtf(re * re + im * im);
                sig[s * PITCH + 151 + k] = atan2f(im, re);
            }
        }
    }
    __syncthreads();

    // ---- encoder layer 1: [202]->[100] -> xbuf (in bufB) ----
    {
        float* xbuf = bufB;
        for (int ii = 0; ii < 13; ++ii) {
            int i = w + 8 * ii;
            if (i < 100) {
                float b = enc_b1[i];
                const float* wr = enc_w1 + (size_t)i * SPD;
#pragma unroll
                for (int p = 0; p < 2; ++p) {
                    int s = lane + 32 * p;
                    xbuf[s * 100 + i] = lrelu(dotAB<101>(sig + s * PITCH, wr) + b);
                }
            }
        }
        __syncthreads();
        // ---- encoder layer 2: [100]->[202] back into sig ----
        for (int ii = 0; ii < 26; ++ii) {
            int i = w + 8 * ii;
            if (i < SPD) {
                float b = enc_b2[i];
                const float* wr = enc_w2 + (size_t)i * 100;
#pragma unroll
                for (int p = 0; p < 2; ++p) {
                    int s = lane + 32 * p;
                    sig[s * PITCH + i] = lrelu(dotAB<50>(xbuf + s * 100, wr) + b);
                }
            }
        }
        __syncthreads();
    }
    // ---- encoder final: [202]->[200] -> h0 in bufB ----
    for (int ii = 0; ii < 25; ++ii) {
        int i = w + 8 * ii;
        float b = enc_bl[i];
        const float* wr = enc_wl + (size_t)i * SPD;
#pragma unroll
        for (int p = 0; p < 2; ++p) {
            int s = lane + 32 * p;
            bufB[s * PITCH + i] = dotAB<101>(sig + s * PITCH, wr) + b;
        }
    }
    __syncthreads();

    const int jbase = w * 25;   // warp owns 25 consecutive j

    // ---- decoder loop; h ping-pongs bufB (t even: hc) <-> bufA ----
    for (int t = 0; t < LD; ++t) {
        float* hc = (t & 1) ? bufA : bufB;
        float* hn = (t & 1) ? bufB : bufA;

        const float dA = din[lane];
        const float dB = din[lane + 32];

        const ulonglong2* hA = (const ulonglong2*)(hc + lane * PITCH);
        const ulonglong2* hB = (const ulonglong2*)(hc + (lane + 32) * PITCH);
        const float* hcA = hc + lane * PITCH;
        const float* hcB = hc + (lane + 32) * PITCH;
        float* hnA = hn + lane * PITCH;
        float* hnB = hn + (lane + 32) * PITCH;

        for (int g = 0; g < 5; ++g) {
            const int j0 = jbase + g * JG;
            const ulonglong2* Wr = (const ulonglong2*)w_hh + (size_t)j0 * 50;
            const ulonglong2* Wz = Wr + 10000;
            const ulonglong2* Wn = Wr + 20000;

            float rA[JG], rB[JG], zA[JG], zB[JG];
            pass2g(hA, hB, Wr, Wz, rA, rB, zA, zB);
#pragma unroll
            for (int u = 0; u < JG; ++u) {
                const int j = j0 + u;
                float bhr = b_hh[j], xr0 = b_ih[j], wir = w_ih[j];
                float bhz = b_hh[HD + j], xz0 = b_ih[HD + j], wiz = w_ih[HD + j];
                rA[u] = sigm(fmaf(dA, wir, xr0) + rA[u] + bhr);
                rB[u] = sigm(fmaf(dB, wir, xr0) + rB[u] + bhr);
                zA[u] = sigm(fmaf(dA, wiz, xz0) + zA[u] + bhz);
                zB[u] = sigm(fmaf(dB, wiz, xz0) + zB[u] + bhz);
            }
            float nA[JG], nB[JG];
            pass1g(hA, hB, Wn, nA, nB);
#pragma unroll
            for (int u = 0; u < JG; ++u) {
                const int j = j0 + u;
                float bhn = b_hh[2 * HD + j], xn0 = b_ih[2 * HD + j], win = w_ih[2 * HD + j];
                float nvA = tanh_f(fmaf(dA, win, xn0) + rA[u] * (nA[u] + bhn));
                float nvB = tanh_f(fmaf(dB, win, xn0) + rB[u] * (nB[u] + bhn));
                hnA[j] = (1.f - zA[u]) * nvA + zA[u] * hcA[j];
                hnB[j] = (1.f - zB[u]) * nvB + zB[u] * hcB[j];
            }
        }
        __syncthreads();

        // hc is now dead: overlay scratch there
        float* xbuf = hc;               // 64*100
        float* y2b  = hc + BT * 100;    // 64*52

        // dec layer 1: [200]->[100]
        for (int ii = 0; ii < 13; ++ii) {
            int i = w + 8 * ii;
            if (i < 100) {
                float b = dec_b1[i];
                const float* wr1 = dec_w1 + (size_t)i * HD;
#pragma unroll
                for (int p = 0; p < 2; ++p) {
                    int s = lane + 32 * p;
                    xbuf[s * 100 + i] = lrelu(dotAB<100>(hn + s * PITCH, wr1) + b);
                }
            }
        }
        __syncthreads();
        // dec layer 2: [100]->[50]
        for (int ii = 0; ii < 7; ++ii) {
            int i = w + 8 * ii;
            if (i < 50) {
                float b = dec_b2[i];
                const float* wr2 = dec_w2 + (size_t)i * 100;
#pragma unroll
                for (int p = 0; p < 2; ++p) {
                    int s = lane + 32 * p;
                    y2b[s * 52 + i] = lrelu(dotAB<50>(xbuf + s * 100, wr2) + b);
                }
            }
        }
        __syncthreads();
        // dec layer 3: [50]->[1]
        if (tid < BT) {
            int s = tid;
            float v = dotAB<25>(y2b + s * 52, dec_w3) + dec_b3[0];
            out[((size_t)(cta * BT + s)) * LD + t] = v;
            din[s] = v;
        }
        __syncthreads();
    }
}

extern "C" void kernel_launch(void* const* d_in, const int* in_sizes, int n_in,
                              void* d_out, int out_size) {
    const float* enc_in = (const float*)d_in[0];
    const float* enc_w1 = (const float*)d_in[1];
    const float* enc_b1 = (const float*)d_in[2];
    const float* enc_w2 = (const float*)d_in[3];
    const float* enc_b2 = (const float*)d_in[4];
    const float* enc_wl = (const float*)d_in[5];
    const float* enc_bl = (const float*)d_in[6];
    const float* w_ih   = (const float*)d_in[7];
    const float* w_hh   = (const float*)d_in[8];
    const float* b_ih   = (const float*)d_in[9];
    const float* b_hh   = (const float*)d_in[10];
    const float* dec_w1 = (const float*)d_in[11];
    const float* dec_b1 = (const float*)d_in[12];
    const float* dec_w2 = (const float*)d_in[13];
    const float* dec_b2 = (const float*)d_in[14];
    const float* dec_w3 = (const float*)d_in[15];
    const float* dec_b3 = (const float*)d_in[16];
    float* out = (float*)d_out;

    cudaFuncSetAttribute(seq2seq_gru_kernel,
                         cudaFuncAttributeMaxDynamicSharedMemorySize, SMEM_BYTES);
    seq2seq_gru_kernel<<<NS / BT, THREADS, SMEM_BYTES>>>(
        enc_in, enc_w1, enc_b1, enc_w2, enc_b2, enc_wl, enc_bl,
        w_ih, w_hh, b_ih, b_hh,
        dec_w1, dec_b1, dec_w2, dec_b2, dec_w3, dec_b3, out);
}

// round 7
// speedup vs baseline: 1.3801x; 1.1341x over previous
#include <cuda_runtime.h>
#include <math.h>

#define NS 131072
#define LE 100
#define LD 50
#define HD 200
#define SPD 202
#define BT 64
#define THREADS 256
#define HP 204
#define Y1P 104
#define Y2P 52
#define TP 224
#define TP2 112

typedef unsigned long long ull;

__device__ __forceinline__ ull fma2(ull a, ull b, ull c) {
    ull d;
    asm("fma.rn.f32x2 %0, %1, %2, %3;" : "=l"(d) : "l"(a), "l"(b), "l"(c));
    return d;
}
__device__ __forceinline__ float red2(ull v) {
    float lo, hi;
    asm("mov.b64 {%0, %1}, %2;" : "=f"(lo), "=f"(hi) : "l"(v));
    return lo + hi;
}
__device__ __forceinline__ ull pk(float lo, float hi) {
    ull r;
    asm("mov.b64 %0, {%1, %2};" : "=l"(r) : "f"(lo), "f"(hi));
    return r;
}

template <int N2>
__device__ __forceinline__ float dotAB(const float* __restrict__ a, const float* __restrict__ b) {
    const ulonglong2* A2 = (const ulonglong2*)a;
    const ull* B = (const ull*)b;
    ull a0 = 0ull, a1 = 0ull;
#pragma unroll
    for (int i = 0; i < N2 / 2; ++i) {
        ulonglong2 x = A2[i];
        a0 = fma2(x.x, B[2 * i], a0);
        a1 = fma2(x.y, B[2 * i + 1], a1);
    }
    if (N2 & 1) a0 = fma2(((const ull*)a)[N2 - 1], B[N2 - 1], a0);
    return red2(a0) + red2(a1);
}

__device__ __forceinline__ float lrelu(float x) { return x > 0.f ? x : 0.01f * x; }
__device__ __forceinline__ float sigm(float x) { return 1.0f / (1.0f + __expf(-x)); }
__device__ __forceinline__ float tanh_f(float x) {
    float t = __expf(-2.0f * fabsf(x));
    float r = (1.0f - t) / (1.0f + t);
    return copysignf(r, x);
}

// smem map (floats)
#define OFF_H    0        // 64*204 = 13056 (sig, then h in-place)
#define OFF_Y1   13056    // 6656 (xbuf / h0 tmp / y1 / y2)
#define OFF_T0   19712    // 2688 tile 0
#define OFF_T1   22400    // 2688 tile 1
#define OFF_GC   25088    // 200*8 gate consts
#define OFF_B1   26688    // 100
#define OFF_B2   26788    // 50
#define OFF_W3   26838    // 50
#define OFF_B3   26888
#define OFF_DIN  26896    // 64
#define OFF_CT   26960    // 100
#define OFF_ST   27060    // 100
#define SMEM_FLOATS 27160
#define SMEM_BYTES  (SMEM_FLOATS * 4)

__device__ __forceinline__ void stage_rows200(float* buf, const float* __restrict__ W,
                                              int r0, int nrows, int tid) {
    if (tid < 224) {
        int oct = tid / 28, c = tid - oct * 28;
        bool real = (c < 25);
        int soff = 25 * oct + c;
#pragma unroll
        for (int lr = 0; lr < 12; ++lr)
            if (lr < nrows)
                buf[lr * TP + tid] = real ? W[(size_t)(r0 + lr) * 200 + soff] : 0.f;
    }
}
__device__ __forceinline__ void stage_gru(float* buf, const float* __restrict__ w_hh,
                                          int j0, int tid) {
    if (tid < 224) {
        int oct = tid / 28, c = tid - oct * 28;
        bool real = (c < 25);
        int soff = 25 * oct + c;
#pragma unroll
        for (int jj = 0; jj < 4; ++jj)
#pragma unroll
            for (int g = 0; g < 3; ++g)
                buf[(jj * 3 + g) * TP + tid] =
                    real ? w_hh[(size_t)(g * 200 + j0 + jj) * 200 + soff] : 0.f;
    }
}
__device__ __forceinline__ void stage_rows100(float* buf, const float* __restrict__ W,
                                              int r0, int nrows, int tid) {
    if (tid < 112) {
        int q = tid / 28, c = tid - q * 28;
        bool real = (c < 25);
        int soff = 25 * q + c;
#pragma unroll
        for (int lr = 0; lr < 12; ++lr)
            if (lr < nrows)
                buf[lr * TP2 + tid] = real ? W[(size_t)(r0 + lr) * 100 + soff] : 0.f;
    }
}

__global__ void __launch_bounds__(THREADS, 2)
seq2seq_gru_kernel(
    const float* __restrict__ enc_in,
    const float* __restrict__ enc_w1, const float* __restrict__ enc_b1,
    const float* __restrict__ enc_w2, const float* __restrict__ enc_b2,
    const float* __restrict__ enc_wl, const float* __restrict__ enc_bl,
    const float* __restrict__ w_ih,  const float* __restrict__ w_hh,
    const float* __restrict__ b_ih,  const float* __restrict__ b_hh,
    const float* __restrict__ dec_w1, const float* __restrict__ dec_b1,
    const float* __restrict__ dec_w2, const float* __restrict__ dec_b2,
    const float* __restrict__ dec_w3, const float* __restrict__ dec_b3,
    float* __restrict__ out)
{
    extern __shared__ float sm[];
    float* hbuf = sm + OFF_H;
    float* smY1 = sm + OFF_Y1;
    float* tb0  = sm + OFF_T0;
    float* tb1  = sm + OFF_T1;
    float* gc   = sm + OFF_GC;
    float* cb1  = sm + OFF_B1;
    float* cb2  = sm + OFF_B2;
    float* w3s  = sm + OFF_W3;
    float* b3s  = sm + OFF_B3;
    float* din  = sm + OFF_DIN;
    float* ctab = sm + OFF_CT;
    float* stab = sm + OFF_ST;

    const int tid  = threadIdx.x;
    const int lane = tid & 31;
    const int w    = tid >> 5;
    const int cta  = blockIdx.x;
    const float* inbase = enc_in + (size_t)cta * BT * LE;
    float* sig = hbuf;

    for (int idx = tid; idx < BT * LE; idx += THREADS) {
        int s = idx / LE, t = idx - s * LE;
        sig[s * HP + t] = inbase[idx];
    }
    if (tid < 100) {
        float u = (float)tid / 50.0f;
        ctab[tid] = cospif(u);
        stab[tid] = sinpif(u);
    }
    if (tid < BT) din[tid] = inbase[tid * LE + (LE - 1)];
    if (tid < 200) {
        int j = tid;
        gc[j * 8 + 0] = b_ih[j] + b_hh[j];
        gc[j * 8 + 1] = b_ih[HD + j] + b_hh[HD + j];
        gc[j * 8 + 2] = b_hh[2 * HD + j];
        gc[j * 8 + 3] = b_ih[2 * HD + j];
        gc[j * 8 + 4] = w_ih[j];
        gc[j * 8 + 5] = w_ih[HD + j];
        gc[j * 8 + 6] = w_ih[2 * HD + j];
        gc[j * 8 + 7] = 0.f;
    }
    if (tid < 100) cb1[tid] = dec_b1[tid];
    if (tid < 50)  { cb2[tid] = dec_b2[tid]; w3s[tid] = dec_w3[tid]; }
    if (tid == 0)  b3s[0] = dec_b3[0];
    __syncthreads();

    // DFT features
    for (int kk = 0; kk < 7; ++kk) {
        int k = w + 8 * kk;
        if (k < 51) {
#pragma unroll
            for (int p = 0; p < 2; ++p) {
                int s = lane + 32 * p;
                const float* xr = sig + s * HP;
                float re = 0.f, im = 0.f;
                int m = 0;
                for (int t = 0; t < LE; ++t) {
                    float xv = xr[t];
                    re += xv * ctab[m];
                    im -= xv * stab[m];
                    m += k; if (m >= 100) m -= 100;
                }
                re *= 0.01f; im *= 0.01f;
                if (k == 0 || k == 50) im = 0.0f;
                sig[s * HP + 100 + k] = sqrtf(re * re + im * im);
                sig[s * HP + 151 + k] = atan2f(im, re);
            }
        }
    }
    __syncthreads();

    // encoder L1 [202]->[100]
    {
        float* xbuf = smY1;
        for (int ii = 0; ii < 13; ++ii) {
            int i = w + 8 * ii;
            if (i < 100) {
                float b = enc_b1[i];
                const float* wr = enc_w1 + (size_t)i * SPD;
#pragma unroll
                for (int p = 0; p < 2; ++p) {
                    int s = lane + 32 * p;
                    xbuf[s * 100 + i] = lrelu(dotAB<101>(sig + s * HP, wr) + b);
                }
            }
        }
        __syncthreads();
        // encoder L2 [100]->[202] back into sig
        for (int ii = 0; ii < 26; ++ii) {
            int i = w + 8 * ii;
            if (i < SPD) {
                float b = enc_b2[i];
                const float* wr = enc_w2 + (size_t)i * 100;
#pragma unroll
                for (int p = 0; p < 2; ++p) {
                    int s = lane + 32 * p;
                    sig[s * HP + i] = lrelu(dotAB<50>(xbuf + s * 100, wr) + b);
                }
            }
        }
        __syncthreads();
    }
    // encoder final [202]->[200] -> h0 (in-place via tmp, two halves)
    for (int half = 0; half < 2; ++half) {
        float* tmp = smY1;
        for (int ii = 0; ii < 25; ++ii) {
            int i = w + 8 * ii;
            int s = lane + 32 * half;
            tmp[lane * 200 + i] = dotAB<101>(sig + s * HP, enc_wl + (size_t)i * SPD) + enc_bl[i];
        }
        __syncthreads();
        for (int idx = tid; idx < 32 * 200; idx += THREADS) {
            int sp_ = idx / 200, i = idx - sp_ * 200;
            hbuf[(32 * half + sp_) * HP + i] = tmp[idx];
        }
        __syncthreads();
    }

    // decode: lane = oct*4 + sp ; warp owns samples w*8 .. w*8+7
    const int oct = lane >> 2;
    const int sp  = lane & 3;
    const int sA  = w * 8 + sp;
    const int sB  = sA + 4;

    for (int t = 0; t < LD; ++t) {
        ull ha[14], hbv[14];
        {
            float ta[28], tb_[28];
#pragma unroll
            for (int c = 0; c < 25; ++c) {
                ta[c]  = hbuf[sA * HP + 25 * oct + c];
                tb_[c] = hbuf[sB * HP + 25 * oct + c];
            }
#pragma unroll
            for (int c = 25; c < 28; ++c) { ta[c] = 0.f; tb_[c] = 0.f; }
#pragma unroll
            for (int c = 0; c < 14; ++c) {
                ha[c]  = pk(ta[2 * c], ta[2 * c + 1]);
                hbv[c] = pk(tb_[2 * c], tb_[2 * c + 1]);
            }
        }
        const float dA = din[sA];
        const float dB = din[sB];

        // ---- GRU: 50 tiles of 4 j ----
        stage_gru(tb0, w_hh, 0, tid);
        __syncthreads();
#pragma unroll 1
        for (int k = 0; k < 50; ++k) {
            float* cur = (k & 1) ? tb1 : tb0;
            float* nxt = (k & 1) ? tb0 : tb1;
            if (k + 1 < 50) stage_gru(nxt, w_hh, (k + 1) * 4, tid);
            const int j0 = k * 4;
#pragma unroll 1
            for (int jj = 0; jj < 4; ++jj) {
                const int j = j0 + jj;
                const ulonglong2* Wr2 = (const ulonglong2*)(cur + (jj * 3 + 0) * TP + oct * 28);
                const ulonglong2* Wz2 = (const ulonglong2*)(cur + (jj * 3 + 1) * TP + oct * 28);
                const ulonglong2* Wn2 = (const ulonglong2*)(cur + (jj * 3 + 2) * TP + oct * 28);
                ull aR0 = 0, aR1 = 0, aZ0 = 0, aZ1 = 0, aN0 = 0, aN1 = 0;
#pragma unroll
                for (int c = 0; c < 7; ++c) {
                    ulonglong2 wr = Wr2[c];
                    aR0 = fma2(ha[2 * c], wr.x, aR0);  aR0 = fma2(ha[2 * c + 1], wr.y, aR0);
                    aR1 = fma2(hbv[2 * c], wr.x, aR1); aR1 = fma2(hbv[2 * c + 1], wr.y, aR1);
                    ulonglong2 wz = Wz2[c];
                    aZ0 = fma2(ha[2 * c], wz.x, aZ0);  aZ0 = fma2(ha[2 * c + 1], wz.y, aZ0);
                    aZ1 = fma2(hbv[2 * c], wz.x, aZ1); aZ1 = fma2(hbv[2 * c + 1], wz.y, aZ1);
                    ulonglong2 wn = Wn2[c];
                    aN0 = fma2(ha[2 * c], wn.x, aN0);  aN0 = fma2(ha[2 * c + 1], wn.y, aN0);
                    aN1 = fma2(hbv[2 * c], wn.x, aN1); aN1 = fma2(hbv[2 * c + 1], wn.y, aN1);
                }
                float dR0 = red2(aR0), dR1 = red2(aR1);
                float dZ0 = red2(aZ0), dZ1 = red2(aZ1);
                float dN0 = red2(aN0), dN1 = red2(aN1);
#pragma unroll
                for (int m = 4; m <= 16; m <<= 1) {
                    dR0 += __shfl_xor_sync(0xffffffffu, dR0, m);
                    dR1 += __shfl_xor_sync(0xffffffffu, dR1, m);
                    dZ0 += __shfl_xor_sync(0xffffffffu, dZ0, m);
                    dZ1 += __shfl_xor_sync(0xffffffffu, dZ1, m);
                    dN0 += __shfl_xor_sync(0xffffffffu, dN0, m);
                    dN1 += __shfl_xor_sync(0xffffffffu, dN1, m);
                }
                float4 g0 = *(const float4*)(gc + j * 8);
                float4 g1 = *(const float4*)(gc + j * 8 + 4);
                float rA = sigm(fmaf(dA, g1.x, g0.x) + dR0);
                float zA = sigm(fmaf(dA, g1.y, g0.y) + dZ0);
                float nA = tanh_f(fmaf(dA, g1.z, g0.w) + rA * (dN0 + g0.z));
                float rB = sigm(fmaf(dB, g1.x, g0.x) + dR1);
                float zB = sigm(fmaf(dB, g1.y, g0.y) + dZ1);
                float nB = tanh_f(fmaf(dB, g1.z, g0.w) + rB * (dN1 + g0.z));
                if (oct == 0) {
                    float hoA = hbuf[sA * HP + j];
                    hbuf[sA * HP + j] = (1.f - zA) * nA + zA * hoA;
                    float hoB = hbuf[sB * HP + j];
                    hbuf[sB * HP + j] = (1.f - zB) * nB + zB * hoB;
                }
            }
            __syncthreads();
        }

        // ---- dec L1 [200]->[100] ----
        {
            float ta[28], tb_[28];
#pragma unroll
            for (int c = 0; c < 25; ++c) {
                ta[c]  = hbuf[sA * HP + 25 * oct + c];
                tb_[c] = hbuf[sB * HP + 25 * oct + c];
            }
#pragma unroll
            for (int c = 25; c < 28; ++c) { ta[c] = 0.f; tb_[c] = 0.f; }
#pragma unroll
            for (int c = 0; c < 14; ++c) {
                ha[c]  = pk(ta[2 * c], ta[2 * c + 1]);
                hbv[c] = pk(tb_[2 * c], tb_[2 * c + 1]);
            }
        }
        stage_rows200(tb0, dec_w1, 0, 12, tid);
        __syncthreads();
#pragma unroll 1
        for (int k = 0; k < 9; ++k) {
            float* cur = (k & 1) ? tb1 : tb0;
            float* nxt = (k & 1) ? tb0 : tb1;
            if (k + 1 < 9) {
                int r0n = (k + 1) * 12;
                stage_rows200(nxt, dec_w1, r0n, min(12, 100 - r0n), tid);
            }
            const int r0 = k * 12;
            const int nr = min(12, 100 - r0);
#pragma unroll 1
            for (int lr = 0; lr < nr; ++lr) {
                const int row = r0 + lr;
                const ulonglong2* W2 = (const ulonglong2*)(cur + lr * TP + oct * 28);
                ull a0 = 0, a1 = 0;
#pragma unroll
                for (int c = 0; c < 7; ++c) {
                    ulonglong2 wv = W2[c];
                    a0 = fma2(ha[2 * c], wv.x, a0);  a0 = fma2(ha[2 * c + 1], wv.y, a0);
                    a1 = fma2(hbv[2 * c], wv.x, a1); a1 = fma2(hbv[2 * c + 1], wv.y, a1);
                }
                float d0 = red2(a0), d1 = red2(a1);
#pragma unroll
                for (int m = 4; m <= 16; m <<= 1) {
                    d0 += __shfl_xor_sync(0xffffffffu, d0, m);
                    d1 += __shfl_xor_sync(0xffffffffu, d1, m);
                }
                if (oct == 0) {
                    float b = cb1[row];
                    smY1[sA * Y1P + row] = lrelu(d0 + b);
                    smY1[sB * Y1P + row] = lrelu(d1 + b);
                }
            }
            __syncthreads();
        }

        // ---- dec L2 [100]->[50] ----
        const int q2 = lane >> 3;
        const int s2 = lane & 7;
        const int samp = w * 8 + s2;
        ull ya[14];
        {
            float tv[28];
#pragma unroll
            for (int c = 0; c < 25; ++c) tv[c] = smY1[samp * Y1P + 25 * q2 + c];
#pragma unroll
            for (int c = 25; c < 28; ++c) tv[c] = 0.f;
#pragma unroll
            for (int c = 0; c < 14; ++c) ya[c] = pk(tv[2 * c], tv[2 * c + 1]);
        }
        stage_rows100(tb0, dec_w2, 0, 12, tid);
        __syncthreads();
        float* smY2 = smY1;
#pragma unroll 1
        for (int k = 0; k < 5; ++k) {
            float* cur = (k & 1) ? tb1 : tb0;
            float* nxt = (k & 1) ? tb0 : tb1;
            if (k + 1 < 5) {
                int r0n = (k + 1) * 12;
                stage_rows100(nxt, dec_w2, r0n, min(12, 50 - r0n), tid);
            }
            const int r0 = k * 12;
            const int nr = min(12, 50 - r0);
#pragma unroll 1
            for (int lr = 0; lr < nr; ++lr) {
                const int row = r0 + lr;
                const ulonglong2* W2 = (const ulonglong2*)(cur + lr * TP2 + q2 * 28);
                ull a0 = 0;
#pragma unroll
                for (int c = 0; c < 7; ++c) {
                    ulonglong2 wv = W2[c];
                    a0 = fma2(ya[2 * c], wv.x, a0);
                    a0 = fma2(ya[2 * c + 1], wv.y, a0);
                }
                float d0 = red2(a0);
#pragma unroll
                for (int m = 8; m <= 16; m <<= 1)
                    d0 += __shfl_xor_sync(0xffffffffu, d0, m);
                if (q2 == 0)
                    smY2[samp * Y2P + row] = lrelu(d0 + cb2[row]);
            }
            __syncthreads();
        }

        // ---- dec L3 + feedback ----
        if (tid < BT) {
            float acc = b3s[0];
            for (int c = 0; c < 50; ++c)
                acc += smY2[tid * Y2P + c] * w3s[c];
            out[((size_t)(cta * BT + tid)) * LD + t] = acc;
            din[tid] = acc;
        }
        __syncthreads();
    }
}

extern "C" void kernel_launch(void* const* d_in, const int* in_sizes, int n_in,
                              void* d_out, int out_size) {
    const float* enc_in = (const float*)d_in[0];
    const float* enc_w1 = (const float*)d_in[1];
    const float* enc_b1 = (const float*)d_in[2];
    const float* enc_w2 = (const float*)d_in[3];
    const float* enc_b2 = (const float*)d_in[4];
    const float* enc_wl = (const float*)d_in[5];
    const float* enc_bl = (const float*)d_in[6];
    const float* w_ih   = (const float*)d_in[7];
    const float* w_hh   = (const float*)d_in[8];
    const float* b_ih   = (const float*)d_in[9];
    const float* b_hh   = (const float*)d_in[10];
    const float* dec_w1 = (const float*)d_in[11];
    const float* dec_b1 = (const float*)d_in[12];
    const float* dec_w2 = (const float*)d_in[13];
    const float* dec_b2 = (const float*)d_in[14];
    const float* dec_w3 = (const float*)d_in[15];
    const float* dec_b3 = (const float*)d_in[16];
    float* out = (float*)d_out;

    cudaFuncSetAttribute(seq2seq_gru_kernel,
                         cudaFuncAttributeMaxDynamicSharedMemorySize, SMEM_BYTES);
    seq2seq_gru_kernel<<<NS / BT, THREADS, SMEM_BYTES>>>(
        enc_in, enc_w1, enc_b1, enc_w2, enc_b2, enc_wl, enc_bl,
        w_ih, w_hh, b_ih, b_hh,
        dec_w1, dec_b1, dec_w2, dec_b2, dec_w3, dec_b3, out);
}

// round 8
// speedup vs baseline: 1.7229x; 1.2484x over previous
#include <cuda_runtime.h>
#include <math.h>

#define NS 131072
#define LE 100
#define LD 50
#define HD 200
#define SPD 202
#define BT 64
#define THREADS 256
#define HP 204
#define Y1P 104
#define Y2P 52
#define TP 224
#define TP2 112

typedef unsigned long long ull;

__device__ __forceinline__ ull fma2(ull a, ull b, ull c) {
    ull d;
    asm("fma.rn.f32x2 %0, %1, %2, %3;" : "=l"(d) : "l"(a), "l"(b), "l"(c));
    return d;
}
__device__ __forceinline__ float red2(ull v) {
    float lo, hi;
    asm("mov.b64 {%0, %1}, %2;" : "=f"(lo), "=f"(hi) : "l"(v));
    return lo + hi;
}
__device__ __forceinline__ ull pk(float lo, float hi) {
    ull r;
    asm("mov.b64 %0, {%1, %2};" : "=l"(r) : "f"(lo), "f"(hi));
    return r;
}

template <int N2>
__device__ __forceinline__ float dotAB(const float* __restrict__ a, const float* __restrict__ b) {
    const ulonglong2* A2 = (const ulonglong2*)a;
    const ull* B = (const ull*)b;
    ull a0 = 0ull, a1 = 0ull;
#pragma unroll
    for (int i = 0; i < N2 / 2; ++i) {
        ulonglong2 x = A2[i];
        a0 = fma2(x.x, B[2 * i], a0);
        a1 = fma2(x.y, B[2 * i + 1], a1);
    }
    if (N2 & 1) a0 = fma2(((const ull*)a)[N2 - 1], B[N2 - 1], a0);
    return red2(a0) + red2(a1);
}

__device__ __forceinline__ float lrelu(float x) { return x > 0.f ? x : 0.01f * x; }
__device__ __forceinline__ float sigm(float x) {
    return __fdividef(1.0f, 1.0f + __expf(-x));
}
__device__ __forceinline__ float tanh_f(float x) {
    float t = __expf(-2.0f * fabsf(x));
    float r = __fdividef(1.0f - t, 1.0f + t);
    return copysignf(r, x);
}

// smem map (floats)
#define OFF_H    0        // 13056 (sig, then h in-place)
#define OFF_Y1   13056    // 6656 (xbuf/h0 tmp/y1/y2; GRU tile buf B)
#define OFF_TA   19712    // 5376 (GRU tile buf A; dec tiles T0/T1 inside)
#define OFF_T0   19712    // 2688 dec tile 0
#define OFF_T1   22400    // 2688 dec tile 1
#define OFF_GC   25088    // 1600 gate consts
#define OFF_B1   26688
#define OFF_B2   26788
#define OFF_W3   26838
#define OFF_B3   26888
#define OFF_DIN  26892
#define OFF_CT   26956
#define OFF_ST   27056
#define SMEM_FLOATS 27156
#define SMEM_BYTES  (SMEM_FLOATS * 4)

__device__ __forceinline__ void stage_rows200(float* buf, const float* __restrict__ W,
                                              int r0, int nrows, int tid) {
    if (tid < 224) {
        int oct = tid / 28, c = tid - oct * 28;
        bool real = (c < 25);
        int soff = 25 * oct + c;
#pragma unroll
        for (int lr = 0; lr < 12; ++lr)
            if (lr < nrows)
                buf[lr * TP + tid] = real ? W[(size_t)(r0 + lr) * 200 + soff] : 0.f;
    }
}
// 8 j's -> 24 rows: (jj*3+g) = W_{r,z,n}[j0+jj]
__device__ __forceinline__ void stage_gru8(float* buf, const float* __restrict__ w_hh,
                                           int j0, int tid) {
    if (tid < 224) {
        int oct = tid / 28, c = tid - oct * 28;
        bool real = (c < 25);
        int soff = 25 * oct + c;
#pragma unroll
        for (int jj = 0; jj < 8; ++jj)
#pragma unroll
            for (int g = 0; g < 3; ++g)
                buf[(jj * 3 + g) * TP + tid] =
                    real ? w_hh[(size_t)(g * 200 + j0 + jj) * 200 + soff] : 0.f;
    }
}
__device__ __forceinline__ void stage_rows100(float* buf, const float* __restrict__ W,
                                              int r0, int nrows, int tid) {
    if (tid < 112) {
        int q = tid / 28, c = tid - q * 28;
        bool real = (c < 25);
        int soff = 25 * q + c;
#pragma unroll
        for (int lr = 0; lr < 12; ++lr)
            if (lr < nrows)
                buf[lr * TP2 + tid] = real ? W[(size_t)(r0 + lr) * 100 + soff] : 0.f;
    }
}

__global__ void __launch_bounds__(THREADS, 2)
seq2seq_gru_kernel(
    const float* __restrict__ enc_in,
    const float* __restrict__ enc_w1, const float* __restrict__ enc_b1,
    const float* __restrict__ enc_w2, const float* __restrict__ enc_b2,
    const float* __restrict__ enc_wl, const float* __restrict__ enc_bl,
    const float* __restrict__ w_ih,  const float* __restrict__ w_hh,
    const float* __restrict__ b_ih,  const float* __restrict__ b_hh,
    const float* __restrict__ dec_w1, const float* __restrict__ dec_b1,
    const float* __restrict__ dec_w2, const float* __restrict__ dec_b2,
    const float* __restrict__ dec_w3, const float* __restrict__ dec_b3,
    float* __restrict__ out)
{
    extern __shared__ float sm[];
    float* hbuf = sm + OFF_H;
    float* smY1 = sm + OFF_Y1;
    float* tbA  = sm + OFF_TA;
    float* tb0  = sm + OFF_T0;
    float* tb1  = sm + OFF_T1;
    float* gc   = sm + OFF_GC;
    float* cb1  = sm + OFF_B1;
    float* cb2  = sm + OFF_B2;
    float* w3s  = sm + OFF_W3;
    float* b3s  = sm + OFF_B3;
    float* din  = sm + OFF_DIN;
    float* ctab = sm + OFF_CT;
    float* stab = sm + OFF_ST;

    const int tid  = threadIdx.x;
    const int lane = tid & 31;
    const int w    = tid >> 5;
    const int cta  = blockIdx.x;
    const float* inbase = enc_in + (size_t)cta * BT * LE;
    float* sig = hbuf;

    for (int idx = tid; idx < BT * LE; idx += THREADS) {
        int s = idx / LE, t = idx - s * LE;
        sig[s * HP + t] = inbase[idx];
    }
    if (tid < 100) {
        float u = (float)tid / 50.0f;
        ctab[tid] = cospif(u);
        stab[tid] = sinpif(u);
    }
    if (tid < BT) din[tid] = inbase[tid * LE + (LE - 1)];
    if (tid < 200) {
        int j = tid;
        gc[j * 8 + 0] = b_ih[j] + b_hh[j];
        gc[j * 8 + 1] = b_ih[HD + j] + b_hh[HD + j];
        gc[j * 8 + 2] = b_hh[2 * HD + j];
        gc[j * 8 + 3] = b_ih[2 * HD + j];
        gc[j * 8 + 4] = w_ih[j];
        gc[j * 8 + 5] = w_ih[HD + j];
        gc[j * 8 + 6] = w_ih[2 * HD + j];
        gc[j * 8 + 7] = 0.f;
    }
    if (tid < 100) cb1[tid] = dec_b1[tid];
    if (tid < 50)  { cb2[tid] = dec_b2[tid]; w3s[tid] = dec_w3[tid]; }
    if (tid == 0)  b3s[0] = dec_b3[0];
    __syncthreads();

    // DFT features
    for (int kk = 0; kk < 7; ++kk) {
        int k = w + 8 * kk;
        if (k < 51) {
#pragma unroll
            for (int p = 0; p < 2; ++p) {
                int s = lane + 32 * p;
                const float* xr = sig + s * HP;
                float re = 0.f, im = 0.f;
                int m = 0;
                for (int t = 0; t < LE; ++t) {
                    float xv = xr[t];
                    re += xv * ctab[m];
                    im -= xv * stab[m];
                    m += k; if (m >= 100) m -= 100;
                }
                re *= 0.01f; im *= 0.01f;
                if (k == 0 || k == 50) im = 0.0f;
                sig[s * HP + 100 + k] = sqrtf(re * re + im * im);
                sig[s * HP + 151 + k] = atan2f(im, re);
            }
        }
    }
    __syncthreads();

    // encoder L1 [202]->[100]
    {
        float* xbuf = smY1;
        for (int ii = 0; ii < 13; ++ii) {
            int i = w + 8 * ii;
            if (i < 100) {
                float b = enc_b1[i];
                const float* wr = enc_w1 + (size_t)i * SPD;
#pragma unroll
                for (int p = 0; p < 2; ++p) {
                    int s = lane + 32 * p;
                    xbuf[s * 100 + i] = lrelu(dotAB<101>(sig + s * HP, wr) + b);
                }
            }
        }
        __syncthreads();
        // encoder L2 [100]->[202]
        for (int ii = 0; ii < 26; ++ii) {
            int i = w + 8 * ii;
            if (i < SPD) {
                float b = enc_b2[i];
                const float* wr = enc_w2 + (size_t)i * 100;
#pragma unroll
                for (int p = 0; p < 2; ++p) {
                    int s = lane + 32 * p;
                    sig[s * HP + i] = lrelu(dotAB<50>(xbuf + s * 100, wr) + b);
                }
            }
        }
        __syncthreads();
    }
    // encoder final [202]->[200] -> h0 in-place via tmp
    for (int half = 0; half < 2; ++half) {
        float* tmp = smY1;
        for (int ii = 0; ii < 25; ++ii) {
            int i = w + 8 * ii;
            int s = lane + 32 * half;
            tmp[lane * 200 + i] = dotAB<101>(sig + s * HP, enc_wl + (size_t)i * SPD) + enc_bl[i];
        }
        __syncthreads();
        for (int idx = tid; idx < 32 * 200; idx += THREADS) {
            int sp_ = idx / 200, i = idx - sp_ * 200;
            hbuf[(32 * half + sp_) * HP + i] = tmp[idx];
        }
        __syncthreads();
    }

    const int oct = lane >> 2;
    const int sp  = lane & 3;
    const int sA  = w * 8 + sp;
    const int sB  = sA + 4;

    for (int t = 0; t < LD; ++t) {
        ull ha[14], hbv[14];
        {
            float ta[28], tb_[28];
#pragma unroll
            for (int c = 0; c < 25; ++c) {
                ta[c]  = hbuf[sA * HP + 25 * oct + c];
                tb_[c] = hbuf[sB * HP + 25 * oct + c];
            }
#pragma unroll
            for (int c = 25; c < 28; ++c) { ta[c] = 0.f; tb_[c] = 0.f; }
#pragma unroll
            for (int c = 0; c < 14; ++c) {
                ha[c]  = pk(ta[2 * c], ta[2 * c + 1]);
                hbv[c] = pk(tb_[2 * c], tb_[2 * c + 1]);
            }
        }
        const float dA = din[sA];
        const float dB = din[sB];

        // ---- GRU: 25 tiles of 8 j, j-paired compute ----
        stage_gru8(tbA, w_hh, 0, tid);
        __syncthreads();
#pragma unroll 1
        for (int k = 0; k < 25; ++k) {
            float* cur = (k & 1) ? smY1 : tbA;
            float* nxt = (k & 1) ? tbA : smY1;
            if (k + 1 < 25) stage_gru8(nxt, w_hh, (k + 1) * 8, tid);
            const int j0 = k * 8;
#pragma unroll 1
            for (int jp = 0; jp < 8; jp += 2) {
                const int j  = j0 + jp;
                const ulonglong2* Ar = (const ulonglong2*)(cur + (jp * 3 + 0) * TP + oct * 28);
                const ulonglong2* Az = (const ulonglong2*)(cur + (jp * 3 + 1) * TP + oct * 28);
                const ulonglong2* An = (const ulonglong2*)(cur + (jp * 3 + 2) * TP + oct * 28);
                const ulonglong2* Br = (const ulonglong2*)(cur + (jp * 3 + 3) * TP + oct * 28);
                const ulonglong2* Bz = (const ulonglong2*)(cur + (jp * 3 + 4) * TP + oct * 28);
                const ulonglong2* Bn = (const ulonglong2*)(cur + (jp * 3 + 5) * TP + oct * 28);
                ull aR0 = 0, aR1 = 0, aZ0 = 0, aZ1 = 0, aN0 = 0, aN1 = 0;
                ull bR0 = 0, bR1 = 0, bZ0 = 0, bZ1 = 0, bN0 = 0, bN1 = 0;
#pragma unroll
                for (int c = 0; c < 7; ++c) {
                    ull hx = ha[2 * c], hy = ha[2 * c + 1];
                    ull gx = hbv[2 * c], gy = hbv[2 * c + 1];
                    ulonglong2 wv;
                    wv = Ar[c];
                    aR0 = fma2(hx, wv.x, aR0); aR0 = fma2(hy, wv.y, aR0);
                    aR1 = fma2(gx, wv.x, aR1); aR1 = fma2(gy, wv.y, aR1);
                    wv = Az[c];
                    aZ0 = fma2(hx, wv.x, aZ0); aZ0 = fma2(hy, wv.y, aZ0);
                    aZ1 = fma2(gx, wv.x, aZ1); aZ1 = fma2(gy, wv.y, aZ1);
                    wv = An[c];
                    aN0 = fma2(hx, wv.x, aN0); aN0 = fma2(hy, wv.y, aN0);
                    aN1 = fma2(gx, wv.x, aN1); aN1 = fma2(gy, wv.y, aN1);
                    wv = Br[c];
                    bR0 = fma2(hx, wv.x, bR0); bR0 = fma2(hy, wv.y, bR0);
                    bR1 = fma2(gx, wv.x, bR1); bR1 = fma2(gy, wv.y, bR1);
                    wv = Bz[c];
                    bZ0 = fma2(hx, wv.x, bZ0); bZ0 = fma2(hy, wv.y, bZ0);
                    bZ1 = fma2(gx, wv.x, bZ1); bZ1 = fma2(gy, wv.y, bZ1);
                    wv = Bn[c];
                    bN0 = fma2(hx, wv.x, bN0); bN0 = fma2(hy, wv.y, bN0);
                    bN1 = fma2(gx, wv.x, bN1); bN1 = fma2(gy, wv.y, bN1);
                }
                float dR0 = red2(aR0), dR1 = red2(aR1);
                float dZ0 = red2(aZ0), dZ1 = red2(aZ1);
                float dN0 = red2(aN0), dN1 = red2(aN1);
                float eR0 = red2(bR0), eR1 = red2(bR1);
                float eZ0 = red2(bZ0), eZ1 = red2(bZ1);
                float eN0 = red2(bN0), eN1 = red2(bN1);
#pragma unroll
                for (int m = 4; m <= 16; m <<= 1) {
                    dR0 += __shfl_xor_sync(0xffffffffu, dR0, m);
                    dR1 += __shfl_xor_sync(0xffffffffu, dR1, m);
                    dZ0 += __shfl_xor_sync(0xffffffffu, dZ0, m);
                    dZ1 += __shfl_xor_sync(0xffffffffu, dZ1, m);
                    dN0 += __shfl_xor_sync(0xffffffffu, dN0, m);
                    dN1 += __shfl_xor_sync(0xffffffffu, dN1, m);
                    eR0 += __shfl_xor_sync(0xffffffffu, eR0, m);
                    eR1 += __shfl_xor_sync(0xffffffffu, eR1, m);
                    eZ0 += __shfl_xor_sync(0xffffffffu, eZ0, m);
                    eZ1 += __shfl_xor_sync(0xffffffffu, eZ1, m);
                    eN0 += __shfl_xor_sync(0xffffffffu, eN0, m);
                    eN1 += __shfl_xor_sync(0xffffffffu, eN1, m);
                }
                {
                    float4 g0 = *(const float4*)(gc + j * 8);
                    float4 g1 = *(const float4*)(gc + j * 8 + 4);
                    float rA = sigm(fmaf(dA, g1.x, g0.x) + dR0);
                    float zA = sigm(fmaf(dA, g1.y, g0.y) + dZ0);
                    float nA = tanh_f(fmaf(dA, g1.z, g0.w) + rA * (dN0 + g0.z));
                    float rB = sigm(fmaf(dB, g1.x, g0.x) + dR1);
                    float zB = sigm(fmaf(dB, g1.y, g0.y) + dZ1);
                    float nB = tanh_f(fmaf(dB, g1.z, g0.w) + rB * (dN1 + g0.z));
                    if (oct == 0) {
                        float hoA = hbuf[sA * HP + j];
                        hbuf[sA * HP + j] = (1.f - zA) * nA + zA * hoA;
                        float hoB = hbuf[sB * HP + j];
                        hbuf[sB * HP + j] = (1.f - zB) * nB + zB * hoB;
                    }
                }
                {
                    const int j2 = j + 1;
                    float4 g0 = *(const float4*)(gc + j2 * 8);
                    float4 g1 = *(const float4*)(gc + j2 * 8 + 4);
                    float rA = sigm(fmaf(dA, g1.x, g0.x) + eR0);
                    float zA = sigm(fmaf(dA, g1.y, g0.y) + eZ0);
                    float nA = tanh_f(fmaf(dA, g1.z, g0.w) + rA * (eN0 + g0.z));
                    float rB = sigm(fmaf(dB, g1.x, g0.x) + eR1);
                    float zB = sigm(fmaf(dB, g1.y, g0.y) + eZ1);
                    float nB = tanh_f(fmaf(dB, g1.z, g0.w) + rB * (eN1 + g0.z));
                    if (oct == 0) {
                        float hoA = hbuf[sA * HP + j2];
                        hbuf[sA * HP + j2] = (1.f - zA) * nA + zA * hoA;
                        float hoB = hbuf[sB * HP + j2];
                        hbuf[sB * HP + j2] = (1.f - zB) * nB + zB * hoB;
                    }
                }
            }
            __syncthreads();
        }

        // ---- dec L1 [200]->[100] ----
        {
            float ta[28], tb_[28];
#pragma unroll
            for (int c = 0; c < 25; ++c) {
                ta[c]  = hbuf[sA * HP + 25 * oct + c];
                tb_[c] = hbuf[sB * HP + 25 * oct + c];
            }
#pragma unroll
            for (int c = 25; c < 28; ++c) { ta[c] = 0.f; tb_[c] = 0.f; }
#pragma unroll
            for (int c = 0; c < 14; ++c) {
                ha[c]  = pk(ta[2 * c], ta[2 * c + 1]);
                hbv[c] = pk(tb_[2 * c], tb_[2 * c + 1]);
            }
        }
        stage_rows200(tb0, dec_w1, 0, 12, tid);
        __syncthreads();
#pragma unroll 1
        for (int k = 0; k < 9; ++k) {
            float* cur = (k & 1) ? tb1 : tb0;
            float* nxt = (k & 1) ? tb0 : tb1;
            if (k + 1 < 9) {
                int r0n = (k + 1) * 12;
                stage_rows200(nxt, dec_w1, r0n, min(12, 100 - r0n), tid);
            }
            const int r0 = k * 12;
            const int nr = min(12, 100 - r0);
#pragma unroll 1
            for (int lr = 0; lr < nr; ++lr) {
                const int row = r0 + lr;
                const ulonglong2* W2 = (const ulonglong2*)(cur + lr * TP + oct * 28);
                ull a0 = 0, a1 = 0;
#pragma unroll
                for (int c = 0; c < 7; ++c) {
                    ulonglong2 wv = W2[c];
                    a0 = fma2(ha[2 * c], wv.x, a0);  a0 = fma2(ha[2 * c + 1], wv.y, a0);
                    a1 = fma2(hbv[2 * c], wv.x, a1); a1 = fma2(hbv[2 * c + 1], wv.y, a1);
                }
                float d0 = red2(a0), d1 = red2(a1);
#pragma unroll
                for (int m = 4; m <= 16; m <<= 1) {
                    d0 += __shfl_xor_sync(0xffffffffu, d0, m);
                    d1 += __shfl_xor_sync(0xffffffffu, d1, m);
                }
                if (oct == 0) {
                    float b = cb1[row];
                    smY1[sA * Y1P + row] = lrelu(d0 + b);
                    smY1[sB * Y1P + row] = lrelu(d1 + b);
                }
            }
            __syncthreads();
        }

        // ---- dec L2 [100]->[50] ----
        const int q2 = lane >> 3;
        const int s2 = lane & 7;
        const int samp = w * 8 + s2;
        ull ya[14];
        {
            float tv[28];
#pragma unroll
            for (int c = 0; c < 25; ++c) tv[c] = smY1[samp * Y1P + 25 * q2 + c];
#pragma unroll
            for (int c = 25; c < 28; ++c) tv[c] = 0.f;
#pragma unroll
            for (int c = 0; c < 14; ++c) ya[c] = pk(tv[2 * c], tv[2 * c + 1]);
        }
        stage_rows100(tb0, dec_w2, 0, 12, tid);
        __syncthreads();
        float* smY2 = smY1;
#pragma unroll 1
        for (int k = 0; k < 5; ++k) {
            float* cur = (k & 1) ? tb1 : tb0;
            float* nxt = (k & 1) ? tb0 : tb1;
            if (k + 1 < 5) {
                int r0n = (k + 1) * 12;
                stage_rows100(nxt, dec_w2, r0n, min(12, 50 - r0n), tid);
            }
            const int r0 = k * 12;
            const int nr = min(12, 50 - r0);
#pragma unroll 1
            for (int lr = 0; lr < nr; ++lr) {
                const int row = r0 + lr;
                const ulonglong2* W2 = (const ulonglong2*)(cur + lr * TP2 + q2 * 28);
                ull a0 = 0;
#pragma unroll
                for (int c = 0; c < 7; ++c) {
                    ulonglong2 wv = W2[c];
                    a0 = fma2(ya[2 * c], wv.x, a0);
                    a0 = fma2(ya[2 * c + 1], wv.y, a0);
                }
                float d0 = red2(a0);
#pragma unroll
                for (int m = 8; m <= 16; m <<= 1)
                    d0 += __shfl_xor_sync(0xffffffffu, d0, m);
                if (q2 == 0)
                    smY2[samp * Y2P + row] = lrelu(d0 + cb2[row]);
            }
            __syncthreads();
        }

        // ---- dec L3 + feedback ----
        if (tid < BT) {
            float acc = b3s[0];
            for (int c = 0; c < 50; ++c)
                acc += smY2[tid * Y2P + c] * w3s[c];
            out[((size_t)(cta * BT + tid)) * LD + t] = acc;
            din[tid] = acc;
        }
        __syncthreads();
    }
}

extern "C" void kernel_launch(void* const* d_in, const int* in_sizes, int n_in,
                              void* d_out, int out_size) {
    const float* enc_in = (const float*)d_in[0];
    const float* enc_w1 = (const float*)d_in[1];
    const float* enc_b1 = (const float*)d_in[2];
    const float* enc_w2 = (const float*)d_in[3];
    const float* enc_b2 = (const float*)d_in[4];
    const float* enc_wl = (const float*)d_in[5];
    const float* enc_bl = (const float*)d_in[6];
    const float* w_ih   = (const float*)d_in[7];
    const float* w_hh   = (const float*)d_in[8];
    const float* b_ih   = (const float*)d_in[9];
    const float* b_hh   = (const float*)d_in[10];
    const float* dec_w1 = (const float*)d_in[11];
    const float* dec_b1 = (const float*)d_in[12];
    const float* dec_w2 = (const float*)d_in[13];
    const float* dec_b2 = (const float*)d_in[14];
    const float* dec_w3 = (const float*)d_in[15];
    const float* dec_b3 = (const float*)d_in[16];
    float* out = (float*)d_out;

    cudaFuncSetAttribute(seq2seq_gru_kernel,
                         cudaFuncAttributeMaxDynamicSharedMemorySize, SMEM_BYTES);
    seq2seq_gru_kernel<<<NS / BT, THREADS, SMEM_BYTES>>>(
        enc_in, enc_w1, enc_b1, enc_w2, enc_b2, enc_wl, enc_bl,
        w_ih, w_hh, b_ih, b_hh,
        dec_w1, dec_b1, dec_w2, dec_b2, dec_w3, dec_b3, out);
}